// round 11
// baseline (speedup 1.0000x reference)
#include <cuda_runtime.h>

// ---------------------------------------------------------------------------
// NodeLevelEncoder: 3x GCN (32->128->256->512) + mean pool + 2x degenerate
// LSTM cell (h0=c0=0 => Whh unused, c=i*g) + output projection.
// All fp32. CSR-gather aggregation, no float atomics, symbol-name scratch.
// Index dtype (int32 vs int64) detected at runtime on device.
// ---------------------------------------------------------------------------

#define MAXN 100000
#define MAXE 800000
#define MAXG 64

__device__ __align__(16) float g_bufA[(size_t)MAXN * 512]; // GEMM output (th)
__device__ __align__(16) float g_bufB[(size_t)MAXN * 512]; // aggregated activations
__device__ float g_dinv[MAXN];                 // rsqrt(deg+1)
__device__ int   g_icnt[MAXN];                 // in-degree (no self loop)
__device__ int   g_off[MAXN];                  // CSR offsets (exclusive scan)
__device__ int   g_cur[MAXN];                  // placement cursors
__device__ int   g_psrc[MAXE];                 // edge sources, dst-grouped
__device__ float g_pw[MAXE];                   // edge norms,   dst-grouped
__device__ int   g_bnd[MAXG + 1];              // per-graph node ranges (sorted batch)
__device__ __align__(16) float g_pooled[MAXG * 512];
__device__ __align__(16) float g_gates[MAXG * 1024];
__device__ __align__(16) float g_hl[MAXG * 256];
__device__ int   g_w64;                        // edge_index is int64?
__device__ int   g_b64;                        // batch_idx  is int64?

static inline int cdiv(int a, int b) { return (a + b - 1) / b; }

// ---------------------------------------------------------------------------
// dtype detection. For int64 (LE) data every odd int32 slot is a zero
// high-word; for genuine int32 data odd slots carry real values (~never all 0
// across 64 spread samples). Reads stay inside the first `slots` int32 words,
// valid under BOTH interpretations.
__global__ void k_detect(const int* ei32, int eslots, const int* b32, int bslots) {
    int w64 = 1;
    for (int k = 0; k < 64; k++) {
        long long j = ((long long)(2 * k + 1) * eslots) / 128;
        int idx = (int)(j | 1);
        if (idx < eslots && ei32[idx] != 0) { w64 = 0; break; }
    }
    g_w64 = w64;
    int b64 = 1;
    for (int k = 0; k < 64; k++) {
        long long j = ((long long)(2 * k + 1) * bslots) / 128;
        int idx = (int)(j | 1);
        if (idx < bslots && b32[idx] != 0) { b64 = 0; break; }
    }
    g_b64 = b64;
}

__device__ __forceinline__ int load_idx(const void* p, long long i, int is64) {
    return is64 ? (int)((const long long*)p)[i] : ((const int*)p)[i];
}

// ---------------------------------------------------------------------------
__global__ void k_zero_cnt(int N) {
    int i = blockIdx.x * blockDim.x + threadIdx.x;
    if (i < N) { g_icnt[i] = 0; g_cur[i] = 0; }
}

// count incoming degree per node (int atomics; setup only)
__global__ void k_count(const void* __restrict__ ei, int E, int N) {
    int e = blockIdx.x * blockDim.x + threadIdx.x;
    if (e >= E) return;
    int d = load_idx(ei, (long long)E + e, g_w64);
    if ((unsigned)d < (unsigned)N) atomicAdd(&g_icnt[d], 1);
}

__global__ void k_dinv(int N) {
    int i = blockIdx.x * blockDim.x + threadIdx.x;
    if (i < N) g_dinv[i] = rsqrtf((float)g_icnt[i] + 1.0f);
}

// single-block exclusive scan of icnt -> off
__global__ __launch_bounds__(1024) void k_scan(int N) {
    __shared__ int ssum[1024];
    int tid = threadIdx.x;
    int chunk = (N + 1023) >> 10;
    int a0 = tid * chunk;
    int a1 = min(a0 + chunk, N);
    int s = 0;
    for (int i = a0; i < a1; i++) s += g_icnt[i];
    ssum[tid] = s;
    __syncthreads();
    for (int d = 1; d < 1024; d <<= 1) {
        int v = (tid >= d) ? ssum[tid - d] : 0;
        __syncthreads();
        ssum[tid] += v;
        __syncthreads();
    }
    int run = (tid == 0) ? 0 : ssum[tid - 1];
    for (int i = a0; i < a1; i++) { g_off[i] = run; run += g_icnt[i]; }
}

// place edges into CSR slots (dst-grouped)
__global__ void k_place(const void* __restrict__ ei, int E, int N) {
    int e = blockIdx.x * blockDim.x + threadIdx.x;
    if (e >= E) return;
    int w64 = g_w64;
    int s = load_idx(ei, e, w64);
    int d = load_idx(ei, (long long)E + e, w64);
    if ((unsigned)s >= (unsigned)N || (unsigned)d >= (unsigned)N) return;
    int p = atomicAdd(&g_cur[d], 1);
    int o = g_off[d] + p;
    g_psrc[o] = s;
    g_pw[o] = g_dinv[s] * g_dinv[d];
}

// per-graph node ranges via binary search over SORTED batch_idx
__global__ void k_bounds(const void* __restrict__ batch, int N, int G) {
    int g = threadIdx.x;
    if (g > G) return;
    if (g == G) { g_bnd[G] = N; return; }
    int b64 = g_b64;
    int lo = 0, hi = N;
    while (lo < hi) {
        int mid = (lo + hi) >> 1;
        if (load_idx(batch, mid, b64) < g) lo = mid + 1; else hi = mid;
    }
    g_bnd[g] = lo;
}

// ---------------------------------------------------------------------------
// SGEMM: g_bufA[N,C] = A[N,K] @ B[K,C].  A = Aext (layer 1) or g_bufB.
// BM=BN=64, BK=16, 256 thr, 4x4 microtile.
// ---------------------------------------------------------------------------
__global__ __launch_bounds__(256) void k_sgemm(const float* __restrict__ Aext,
                                               const float* __restrict__ B,
                                               int Nrows, int K, int Ccols) {
    __shared__ __align__(16) float As[16][68];
    __shared__ __align__(16) float Bs[16][64];

    const float* A = Aext ? Aext : g_bufB;
    float* const Cm = g_bufA;

    int tid = threadIdx.x;
    int tx = tid & 15;
    int ty = tid >> 4;
    int row0 = blockIdx.y * 64;
    int col0 = blockIdx.x * 64;

    float acc[4][4];
#pragma unroll
    for (int i = 0; i < 4; i++)
#pragma unroll
        for (int j = 0; j < 4; j++) acc[i][j] = 0.f;

    for (int kt = 0; kt < K; kt += 16) {
#pragma unroll
        for (int i = 0; i < 4; i++) {
            int idx = tid + i * 256;
            int r = idx >> 4;
            int kk = idx & 15;
            int grow = row0 + r;
            As[kk][r] = (grow < Nrows) ? A[(size_t)grow * K + kt + kk] : 0.f;
        }
#pragma unroll
        for (int i = 0; i < 4; i++) {
            int idx = tid + i * 256;
            int kk = idx >> 6;
            int c = idx & 63;
            Bs[kk][c] = B[(size_t)(kt + kk) * Ccols + col0 + c];
        }
        __syncthreads();

#pragma unroll
        for (int kk = 0; kk < 16; kk++) {
            float4 a = *(const float4*)&As[kk][ty * 4];
            float4 b = *(const float4*)&Bs[kk][tx * 4];
            float av[4] = {a.x, a.y, a.z, a.w};
            float bv[4] = {b.x, b.y, b.z, b.w};
#pragma unroll
            for (int i = 0; i < 4; i++)
#pragma unroll
                for (int j = 0; j < 4; j++) acc[i][j] += av[i] * bv[j];
        }
        __syncthreads();
    }

#pragma unroll
    for (int i = 0; i < 4; i++) {
        int grow = row0 + ty * 4 + i;
        if (grow < Nrows) {
            float4 o = make_float4(acc[i][0], acc[i][1], acc[i][2], acc[i][3]);
            *(float4*)&Cm[(size_t)grow * Ccols + col0 + tx * 4] = o;
        }
    }
}

// ---------------------------------------------------------------------------
// Fused GCN aggregation (gather form), g_bufA -> g_bufB:
//   out[n] = relu( sum_{e in CSR(n)} th[src(e)]*w(e) + th[n]*dinv[n]^2 + bias )
// One thread per (node, float4-channel-group). sh = log2(C/4).
// ---------------------------------------------------------------------------
__global__ void k_agg(const float4* __restrict__ bias, int total, int sh) {
    int i = blockIdx.x * blockDim.x + threadIdx.x;
    if (i >= total) return;
    int n = i >> sh;
    int c = i & ((1 << sh) - 1);

    const float4* th = (const float4*)g_bufA;
    float4* out = (float4*)g_bufB;

    float s = g_dinv[n];
    s *= s;
    float4 t = th[i];
    float4 acc = make_float4(t.x * s, t.y * s, t.z * s, t.w * s);

    int e0 = g_off[n];
    int e1 = e0 + g_icnt[n];
    for (int e = e0; e < e1; e++) {
        int sn = g_psrc[e];
        float w = g_pw[e];
        float4 v = th[((size_t)sn << sh) + c];
        acc.x += v.x * w; acc.y += v.y * w; acc.z += v.z * w; acc.w += v.w * w;
    }
    float4 b = bias[c];
    out[i] = make_float4(fmaxf(acc.x + b.x, 0.f), fmaxf(acc.y + b.y, 0.f),
                         fmaxf(acc.z + b.z, 0.f), fmaxf(acc.w + b.w, 0.f));
}

// ---------------------------------------------------------------------------
// mean pool: no atomics. block (g, cg) of 128 threads sums channels
// [cg*128, cg*128+128) over node range g_bnd[g]..g_bnd[g+1].
// ---------------------------------------------------------------------------
__global__ __launch_bounds__(128) void k_pool() {
    int g = blockIdx.x;
    int c = blockIdx.y * 128 + threadIdx.x;   // channel 0..511
    int n0 = g_bnd[g];
    int n1 = g_bnd[g + 1];
    float acc = 0.f;
    for (int n = n0; n < n1; n++) acc += g_bufB[(size_t)n * 512 + c];
    float cntf = (float)(n1 - n0);
    g_pooled[g * 512 + c] = acc / fmaxf(cntf, 1.f);
}

// ---------------------------------------------------------------------------
// out[g][j] = dot(in[g][:In], W[j][:In]) + ba[j] (+ bb[j]).  W row-major.
// in = g_hl if in_sel else g_pooled.  out = out_ext if non-null else g_gates.
// ---------------------------------------------------------------------------
__global__ __launch_bounds__(256) void k_dense(int in_sel,
                                               const float* __restrict__ W,
                                               const float* __restrict__ ba,
                                               const float* __restrict__ bb,
                                               float* out_ext, int In, int Out) {
    __shared__ __align__(16) float sin[512];
    const float* in = in_sel ? g_hl : g_pooled;
    float* out = out_ext ? out_ext : g_gates;
    int g = blockIdx.y;
    for (int k = threadIdx.x; k < In; k += blockDim.x) sin[k] = in[(size_t)g * In + k];
    __syncthreads();
    int j = blockIdx.x * blockDim.x + threadIdx.x;
    if (j >= Out) return;
    float acc = ba[j] + (bb ? bb[j] : 0.f);
    const float4* Wr = (const float4*)(W + (size_t)j * In);
    const float4* xs = (const float4*)sin;
    int k4 = In >> 2;
    for (int k = 0; k < k4; k++) {
        float4 w = Wr[k];
        float4 x = xs[k];
        acc += w.x * x.x + w.y * x.y + w.z * x.z + w.w * x.w;
    }
    out[(size_t)g * Out + j] = acc;
}

// h0=c0=0:  h = sigmoid(o) * tanh( sigmoid(i) * tanh(g) ).  gates in g_gates.
__global__ void k_lstm(int total, int H) {
    int i = blockIdx.x * blockDim.x + threadIdx.x;
    if (i >= total) return;
    int g = i / H;
    int j = i - g * H;
    const float* gr = g_gates + (size_t)g * 4 * H;
    float ii = gr[j];
    float gg = gr[2 * H + j];
    float oo = gr[3 * H + j];
    float si = 1.f / (1.f + expf(-ii));
    float so = 1.f / (1.f + expf(-oo));
    float c = si * tanhf(gg);
    g_hl[i] = so * tanhf(c);
}

// ---------------------------------------------------------------------------
extern "C" void kernel_launch(void* const* d_in, const int* in_sizes, int n_in,
                              void* d_out, int out_size) {
    const float* x     = (const float*)d_in[0];
    const void*  ei    = d_in[1];               // int32 or int64 -> detected
    const void*  batch = d_in[2];               // int32 or int64 -> detected
    const float *W1 = (const float*)d_in[3],  *b1 = (const float*)d_in[4];
    const float *W2 = (const float*)d_in[5],  *b2 = (const float*)d_in[6];
    const float *W3 = (const float*)d_in[7],  *b3 = (const float*)d_in[8];
    const float *Wih0 = (const float*)d_in[9];
    const float *bih0 = (const float*)d_in[11], *bhh0 = (const float*)d_in[12];
    const float *Wih1 = (const float*)d_in[13];
    const float *bih1 = (const float*)d_in[15], *bhh1 = (const float*)d_in[16];
    const float *Wp = (const float*)d_in[17],  *bp = (const float*)d_in[18];
    // Whh0 (d_in[10]) / Whh1 (d_in[14]) are dead: h0 = 0.

    int N = in_sizes[0] / 32;
    int E = in_sizes[1] / 2;
    int G = out_size / 512;

    const int T = 256;

    // ---- dtype detection + CSR + normalization setup ----
    k_detect<<<1, 1>>>((const int*)ei, in_sizes[1], (const int*)batch, in_sizes[2]);
    k_zero_cnt<<<cdiv(N, T), T>>>(N);
    k_count<<<cdiv(E, T), T>>>(ei, E, N);
    k_dinv<<<cdiv(N, T), T>>>(N);
    k_scan<<<1, 1024>>>(N);
    k_place<<<cdiv(E, T), T>>>(ei, E, N);
    k_bounds<<<1, G + 1>>>(batch, N, G);

    // ---- GCN layer 1: 32 -> 128 ----
    {
        const int C = 128, sh = 5, tot = N * (C / 4);
        k_sgemm<<<dim3(C / 64, cdiv(N, 64)), 256>>>(x, W1, N, 32, C);
        k_agg<<<cdiv(tot, T), T>>>((const float4*)b1, tot, sh);
    }
    // ---- GCN layer 2: 128 -> 256 ----
    {
        const int C = 256, sh = 6, tot = N * (C / 4);
        k_sgemm<<<dim3(C / 64, cdiv(N, 64)), 256>>>(nullptr, W2, N, 128, C);
        k_agg<<<cdiv(tot, T), T>>>((const float4*)b2, tot, sh);
    }
    // ---- GCN layer 3: 256 -> 512 ----
    {
        const int C = 512, sh = 7, tot = N * (C / 4);
        k_sgemm<<<dim3(C / 64, cdiv(N, 64)), 256>>>(nullptr, W3, N, 256, C);
        k_agg<<<cdiv(tot, T), T>>>((const float4*)b3, tot, sh);
    }

    // ---- mean pool per graph (no atomics; sorted batch -> ranges) ----
    k_pool<<<dim3(G, 4), 128>>>();

    // ---- LSTM (degenerate, seq_len=1, zero state) + projection ----
    k_dense<<<dim3(4, G), 256>>>(0, Wih0, bih0, bhh0, nullptr, 512, 1024);
    k_lstm<<<cdiv(G * 256, T), T>>>(G * 256, 256);
    k_dense<<<dim3(4, G), 256>>>(1, Wih1, bih1, bhh1, nullptr, 256, 1024);
    k_lstm<<<cdiv(G * 256, T), T>>>(G * 256, 256);
    k_dense<<<dim3(2, G), 256>>>(1, Wp, bp, nullptr, (float*)d_out, 256, 512);
}

// round 12
// speedup vs baseline: 1.3178x; 1.3178x over previous
#include <cuda_runtime.h>

// ---------------------------------------------------------------------------
// NodeLevelEncoder: 3x GCN + mean pool + 2x degenerate LSTM + projection.
// R12: (1) aggregate BEFORE transform (agg is linear => agg(h)@W == agg(h@W)),
//      gathering in the smaller input dim (32/128/256 instead of 128/256/512);
//      (2) 128x128x8 SGEMM with 8x8 microtile and fused bias+relu epilogue.
// Index dtype (int32 vs int64) detected at runtime on device.
// ---------------------------------------------------------------------------

#define MAXN 100000
#define MAXE 800000
#define MAXG 64

__device__ __align__(16) float g_bufA[(size_t)MAXN * 512]; // activations (GEMM out)
__device__ __align__(16) float g_bufB[(size_t)MAXN * 256]; // aggregated (GEMM in)
__device__ float g_dinv[MAXN];
__device__ int   g_icnt[MAXN];
__device__ int   g_off[MAXN];
__device__ int   g_cur[MAXN];
__device__ int   g_psrc[MAXE];
__device__ float g_pw[MAXE];
__device__ int   g_bnd[MAXG + 1];
__device__ __align__(16) float g_pooled[MAXG * 512];
__device__ __align__(16) float g_gates[MAXG * 1024];
__device__ __align__(16) float g_hl[MAXG * 256];
__device__ int   g_w64;
__device__ int   g_b64;

static inline int cdiv(int a, int b) { return (a + b - 1) / b; }

// ---------------------------------------------------------------------------
// dtype detection: int64 (LE) data has zero high-words in odd int32 slots.
__global__ void k_detect(const int* ei32, int eslots, const int* b32, int bslots) {
    int w64 = 1;
    for (int k = 0; k < 64; k++) {
        long long j = ((long long)(2 * k + 1) * eslots) / 128;
        int idx = (int)(j | 1);
        if (idx < eslots && ei32[idx] != 0) { w64 = 0; break; }
    }
    g_w64 = w64;
    int b64 = 1;
    for (int k = 0; k < 64; k++) {
        long long j = ((long long)(2 * k + 1) * bslots) / 128;
        int idx = (int)(j | 1);
        if (idx < bslots && b32[idx] != 0) { b64 = 0; break; }
    }
    g_b64 = b64;
}

__device__ __forceinline__ int load_idx(const void* p, long long i, int is64) {
    return is64 ? (int)((const long long*)p)[i] : ((const int*)p)[i];
}

// ---------------------------------------------------------------------------
__global__ void k_zero_cnt(int N) {
    int i = blockIdx.x * blockDim.x + threadIdx.x;
    if (i < N) { g_icnt[i] = 0; g_cur[i] = 0; }
}

__global__ void k_count(const void* __restrict__ ei, int E, int N) {
    int e = blockIdx.x * blockDim.x + threadIdx.x;
    if (e >= E) return;
    int d = load_idx(ei, (long long)E + e, g_w64);
    if ((unsigned)d < (unsigned)N) atomicAdd(&g_icnt[d], 1);
}

__global__ void k_dinv(int N) {
    int i = blockIdx.x * blockDim.x + threadIdx.x;
    if (i < N) g_dinv[i] = rsqrtf((float)g_icnt[i] + 1.0f);
}

__global__ __launch_bounds__(1024) void k_scan(int N) {
    __shared__ int ssum[1024];
    int tid = threadIdx.x;
    int chunk = (N + 1023) >> 10;
    int a0 = tid * chunk;
    int a1 = min(a0 + chunk, N);
    int s = 0;
    for (int i = a0; i < a1; i++) s += g_icnt[i];
    ssum[tid] = s;
    __syncthreads();
    for (int d = 1; d < 1024; d <<= 1) {
        int v = (tid >= d) ? ssum[tid - d] : 0;
        __syncthreads();
        ssum[tid] += v;
        __syncthreads();
    }
    int run = (tid == 0) ? 0 : ssum[tid - 1];
    for (int i = a0; i < a1; i++) { g_off[i] = run; run += g_icnt[i]; }
}

__global__ void k_place(const void* __restrict__ ei, int E, int N) {
    int e = blockIdx.x * blockDim.x + threadIdx.x;
    if (e >= E) return;
    int w64 = g_w64;
    int s = load_idx(ei, e, w64);
    int d = load_idx(ei, (long long)E + e, w64);
    if ((unsigned)s >= (unsigned)N || (unsigned)d >= (unsigned)N) return;
    int p = atomicAdd(&g_cur[d], 1);
    int o = g_off[d] + p;
    g_psrc[o] = s;
    g_pw[o] = g_dinv[s] * g_dinv[d];
}

__global__ void k_bounds(const void* __restrict__ batch, int N, int G) {
    int g = threadIdx.x;
    if (g > G) return;
    if (g == G) { g_bnd[G] = N; return; }
    int b64 = g_b64;
    int lo = 0, hi = N;
    while (lo < hi) {
        int mid = (lo + hi) >> 1;
        if (load_idx(batch, mid, b64) < g) lo = mid + 1; else hi = mid;
    }
    g_bnd[g] = lo;
}

// ---------------------------------------------------------------------------
// GCN aggregation in INPUT dim (pure gather, before transform):
//   agg[n] = sum_{e in CSR(n)} act[src(e)]*w(e) + act[n]*dinv[n]^2
// src = g_bufA (a_sel=1) or external x (a_sel=0); dst = g_bufB.
// One thread per (node, float4 group). sh = log2(K/4), K in {32,128,256}.
// ---------------------------------------------------------------------------
__global__ void k_agg(int a_sel, const float* __restrict__ ext, int total, int sh) {
    int i = blockIdx.x * blockDim.x + threadIdx.x;
    if (i >= total) return;
    int n = i >> sh;
    int c = i & ((1 << sh) - 1);

    const float4* act = a_sel ? (const float4*)g_bufA : (const float4*)ext;
    float4* out = (float4*)g_bufB;

    float s = g_dinv[n];
    s *= s;
    float4 t = act[i];
    float4 acc = make_float4(t.x * s, t.y * s, t.z * s, t.w * s);

    int e0 = g_off[n];
    int e1 = e0 + g_icnt[n];
    for (int e = e0; e < e1; e++) {
        int sn = g_psrc[e];
        float w = g_pw[e];
        float4 v = act[((size_t)sn << sh) + c];
        acc.x += v.x * w; acc.y += v.y * w; acc.z += v.z * w; acc.w += v.w * w;
    }
    out[i] = acc;
}

// ---------------------------------------------------------------------------
// SGEMM with fused bias+relu: g_bufA[N,C] = relu(g_bufB[N,K] @ W[K,C] + bias)
// BM=BN=128, BK=8, 256 threads, 8x8 microtile (4+4 split for float4 LDS).
// K % 8 == 0 (32/128/256), C % 128 == 0 (128/256/512).
// ---------------------------------------------------------------------------
__global__ __launch_bounds__(256) void k_gemm_relu(const float* __restrict__ W,
                                                   const float* __restrict__ bias,
                                                   int Nrows, int K, int C) {
    __shared__ __align__(16) float As[8][132];
    __shared__ __align__(16) float Bs[8][128];

    const float* A = g_bufB;
    float* const out = g_bufA;

    int tid = threadIdx.x;
    int tx = tid & 15;          // 0..15 -> cols tx*4 and 64+tx*4
    int ty = tid >> 4;          // 0..15 -> rows ty*4 and 64+ty*4
    int row0 = blockIdx.y * 128;
    int col0 = blockIdx.x * 128;

    float acc[8][8];
#pragma unroll
    for (int i = 0; i < 8; i++)
#pragma unroll
        for (int j = 0; j < 8; j++) acc[i][j] = 0.f;

    int ar = tid >> 1;               // 0..127 (A tile row)
    int ak = (tid & 1) * 4;          // 0 or 4 (A tile k)
    int bk = tid >> 5;               // 0..7   (B tile k)
    int bc = (tid & 31) * 4;         // B tile col

    for (int kt = 0; kt < K; kt += 8) {
        int grow = row0 + ar;
        float4 av = make_float4(0.f, 0.f, 0.f, 0.f);
        if (grow < Nrows) av = *(const float4*)&A[(size_t)grow * K + kt + ak];
        As[ak + 0][ar] = av.x;
        As[ak + 1][ar] = av.y;
        As[ak + 2][ar] = av.z;
        As[ak + 3][ar] = av.w;

        *(float4*)&Bs[bk][bc] = *(const float4*)&W[(size_t)(kt + bk) * C + col0 + bc];
        __syncthreads();

#pragma unroll
        for (int k = 0; k < 8; k++) {
            float4 a0 = *(const float4*)&As[k][ty * 4];
            float4 a1 = *(const float4*)&As[k][64 + ty * 4];
            float4 b0 = *(const float4*)&Bs[k][tx * 4];
            float4 b1 = *(const float4*)&Bs[k][64 + tx * 4];
            float aa[8] = {a0.x, a0.y, a0.z, a0.w, a1.x, a1.y, a1.z, a1.w};
            float bb[8] = {b0.x, b0.y, b0.z, b0.w, b1.x, b1.y, b1.z, b1.w};
#pragma unroll
            for (int i = 0; i < 8; i++)
#pragma unroll
                for (int j = 0; j < 8; j++) acc[i][j] += aa[i] * bb[j];
        }
        __syncthreads();
    }

    float4 bv0 = *(const float4*)&bias[col0 + tx * 4];
    float4 bv1 = *(const float4*)&bias[col0 + 64 + tx * 4];
    float bb[8] = {bv0.x, bv0.y, bv0.z, bv0.w, bv1.x, bv1.y, bv1.z, bv1.w};

#pragma unroll
    for (int i = 0; i < 8; i++) {
        int grow = row0 + ((i < 4) ? (ty * 4 + i) : (64 + ty * 4 + i - 4));
        if (grow >= Nrows) continue;
        float4 o0 = make_float4(fmaxf(acc[i][0] + bb[0], 0.f), fmaxf(acc[i][1] + bb[1], 0.f),
                                fmaxf(acc[i][2] + bb[2], 0.f), fmaxf(acc[i][3] + bb[3], 0.f));
        float4 o1 = make_float4(fmaxf(acc[i][4] + bb[4], 0.f), fmaxf(acc[i][5] + bb[5], 0.f),
                                fmaxf(acc[i][6] + bb[6], 0.f), fmaxf(acc[i][7] + bb[7], 0.f));
        *(float4*)&out[(size_t)grow * C + col0 + tx * 4] = o0;
        *(float4*)&out[(size_t)grow * C + col0 + 64 + tx * 4] = o1;
    }
}

// ---------------------------------------------------------------------------
// mean pool over g_bufA (final activations, 512 ch). No atomics.
// ---------------------------------------------------------------------------
__global__ __launch_bounds__(128) void k_pool() {
    int g = blockIdx.x;
    int c = blockIdx.y * 128 + threadIdx.x;   // channel 0..511
    int n0 = g_bnd[g];
    int n1 = g_bnd[g + 1];
    float acc = 0.f;
    for (int n = n0; n < n1; n++) acc += g_bufA[(size_t)n * 512 + c];
    float cntf = (float)(n1 - n0);
    g_pooled[g * 512 + c] = acc / fmaxf(cntf, 1.f);
}

// ---------------------------------------------------------------------------
__global__ __launch_bounds__(256) void k_dense(int in_sel,
                                               const float* __restrict__ W,
                                               const float* __restrict__ ba,
                                               const float* __restrict__ bb,
                                               float* out_ext, int In, int Out) {
    __shared__ __align__(16) float sin[512];
    const float* in = in_sel ? g_hl : g_pooled;
    float* out = out_ext ? out_ext : g_gates;
    int g = blockIdx.y;
    for (int k = threadIdx.x; k < In; k += blockDim.x) sin[k] = in[(size_t)g * In + k];
    __syncthreads();
    int j = blockIdx.x * blockDim.x + threadIdx.x;
    if (j >= Out) return;
    float acc = ba[j] + (bb ? bb[j] : 0.f);
    const float4* Wr = (const float4*)(W + (size_t)j * In);
    const float4* xs = (const float4*)sin;
    int k4 = In >> 2;
    for (int k = 0; k < k4; k++) {
        float4 w = Wr[k];
        float4 x = xs[k];
        acc += w.x * x.x + w.y * x.y + w.z * x.z + w.w * x.w;
    }
    out[(size_t)g * Out + j] = acc;
}

// h0=c0=0:  h = sigmoid(o) * tanh( sigmoid(i) * tanh(g) )
__global__ void k_lstm(int total, int H) {
    int i = blockIdx.x * blockDim.x + threadIdx.x;
    if (i >= total) return;
    int g = i / H;
    int j = i - g * H;
    const float* gr = g_gates + (size_t)g * 4 * H;
    float ii = gr[j];
    float gg = gr[2 * H + j];
    float oo = gr[3 * H + j];
    float si = 1.f / (1.f + expf(-ii));
    float so = 1.f / (1.f + expf(-oo));
    float c = si * tanhf(gg);
    g_hl[i] = so * tanhf(c);
}

// ---------------------------------------------------------------------------
extern "C" void kernel_launch(void* const* d_in, const int* in_sizes, int n_in,
                              void* d_out, int out_size) {
    const float* x     = (const float*)d_in[0];
    const void*  ei    = d_in[1];
    const void*  batch = d_in[2];
    const float *W1 = (const float*)d_in[3],  *b1 = (const float*)d_in[4];
    const float *W2 = (const float*)d_in[5],  *b2 = (const float*)d_in[6];
    const float *W3 = (const float*)d_in[7],  *b3 = (const float*)d_in[8];
    const float *Wih0 = (const float*)d_in[9];
    const float *bih0 = (const float*)d_in[11], *bhh0 = (const float*)d_in[12];
    const float *Wih1 = (const float*)d_in[13];
    const float *bih1 = (const float*)d_in[15], *bhh1 = (const float*)d_in[16];
    const float *Wp = (const float*)d_in[17],  *bp = (const float*)d_in[18];
    // Whh0 (d_in[10]) / Whh1 (d_in[14]) are dead: h0 = 0.

    int N = in_sizes[0] / 32;
    int E = in_sizes[1] / 2;
    int G = out_size / 512;

    const int T = 256;

    // ---- dtype detection + CSR + normalization setup ----
    k_detect<<<1, 1>>>((const int*)ei, in_sizes[1], (const int*)batch, in_sizes[2]);
    k_zero_cnt<<<cdiv(N, T), T>>>(N);
    k_count<<<cdiv(E, T), T>>>(ei, E, N);
    k_dinv<<<cdiv(N, T), T>>>(N);
    k_scan<<<1, 1024>>>(N);
    k_place<<<cdiv(E, T), T>>>(ei, E, N);
    k_bounds<<<1, G + 1>>>(batch, N, G);

    // ---- GCN layer 1: agg(x)[N,32] -> relu(@W1+b1)[N,128] ----
    k_agg<<<cdiv(N * 8, T), T>>>(0, x, N * 8, 3);
    k_gemm_relu<<<dim3(1, cdiv(N, 128)), 256>>>(W1, b1, N, 32, 128);

    // ---- GCN layer 2: agg[N,128] -> relu(@W2+b2)[N,256] ----
    k_agg<<<cdiv(N * 32, T), T>>>(1, nullptr, N * 32, 5);
    k_gemm_relu<<<dim3(2, cdiv(N, 128)), 256>>>(W2, b2, N, 128, 256);

    // ---- GCN layer 3: agg[N,256] -> relu(@W3+b3)[N,512] ----
    k_agg<<<cdiv(N * 64, T), T>>>(1, nullptr, N * 64, 6);
    k_gemm_relu<<<dim3(4, cdiv(N, 128)), 256>>>(W3, b3, N, 256, 512);

    // ---- mean pool per graph ----
    k_pool<<<dim3(G, 4), 128>>>();

    // ---- LSTM (degenerate) + projection ----
    k_dense<<<dim3(4, G), 256>>>(0, Wih0, bih0, bhh0, nullptr, 512, 1024);
    k_lstm<<<cdiv(G * 256, T), T>>>(G * 256, 256);
    k_dense<<<dim3(4, G), 256>>>(1, Wih1, bih1, bhh1, nullptr, 256, 1024);
    k_lstm<<<cdiv(G * 256, T), T>>>(G * 256, 256);
    k_dense<<<dim3(2, G), 256>>>(1, Wp, bp, nullptr, (float*)d_out, 256, 512);
}